// round 13
// baseline (speedup 1.0000x reference)
#include <cuda_runtime.h>
#include <cstdint>

#define H 256
#define W 256
#define K 512
#define Z_THRESHOLD 3.0f
#define EPS 1e-08f

// sqrt(0.5 * log2(e)): folded into inverse scales so gauss = exp2(-(dx'^2+dy'^2))
#define SCALE_C 0.84932180028801904f
// -0.5 * log2(e): z-gaussian directly in log2 domain
#define NHALF_LOG2E -0.72134752044448170f

#define TPB   256            // threads per block (1 image row per block)
#define GRID  H              // 256 blocks, 2 resident per SM
#define NWARP (TPB / 32)

// Cull threshold: max row alpha < 2^-20 ~ 1e-6 -> skipped gaussian perturbs
// a pixel by < ~6e-5 absolute; rel tolerance is 1e-3.
#define CULL_LOG2 -20.0f

// ---------------------------------------------------------------------------
// Fused kernel, log-domain version. Each block owns ONE image row.
//   1) thin prep (2 gaussians/thread via float2 loads): l2w = log2(opacity)
//      - 0.5*log2e*zd^2 (NO exp), division-free row cull
//      t^2 < (l2w - CULL_LOG2)(sx+EPS)^2,
//   2) warp-count compaction of survivor keys (l2w < 0 always, so for the
//      negative-float bit pattern ascending uint64 == descending eff_w,
//      ascending idx on ties -> stable argsort restricted to survivors),
//   3) rank sort over ~8 keys; survivor threads reload raw params from
//      global (cache-hot) and pack straight to csp[rank],
//   4) render: 1 px/thread, 7-instr inner loop.
// ---------------------------------------------------------------------------
__global__ void __launch_bounds__(TPB, 2)
fused_kernel(const float* __restrict__ positions,   // [K,3]
             const float* __restrict__ scales,      // [K,3]
             const float* __restrict__ opacity,     // [K]
             const float* __restrict__ intensity,   // [K]
             const float* __restrict__ z_target,    // [1]
             float* __restrict__ out)               // [H*W]
{
    __shared__ unsigned long long sk[K];  // compacted survivor keys
    __shared__ float4 csp[K];             // rank-ordered survivor params
    __shared__ int    warpCnt[NWARP];

    const int tid  = threadIdx.x;
    const int lane = tid & 31;
    const int wid  = tid >> 5;
    const float fy = (float)blockIdx.x;   // this block's image row

    // ---- thin prep: gaussian pair (2*tid, 2*tid+1) via float2 loads ----
    const float zt = z_target[0];
    const float2* p2 = (const float2*)positions;
    const float2* s2 = (const float2*)scales;
    const float2 pA = p2[3 * tid + 0];    // px0, py0
    const float2 pB = p2[3 * tid + 1];    // pz0, px1
    const float2 pC = p2[3 * tid + 2];    // py1, pz1
    const float2 sA = s2[3 * tid + 0];    // sx0, sy0
    const float2 sB = s2[3 * tid + 1];    // sz0, sx1
    const float2 sC = s2[3 * tid + 2];    // sy1, sz1
    const float2 op = ((const float2*)opacity)[tid];

    const float pxg[2] = {pA.x, pB.y};
    const float pzg[2] = {pB.x, pC.y};
    const float sxg[2] = {sA.x, sB.y};
    const float szg[2] = {sB.x, sC.y};
    const float opg[2] = {op.x, op.y};

    bool kp[2];
    unsigned long long kk[2];

    #pragma unroll
    for (int s = 0; s < 2; ++s) {
        const int g = 2 * tid + s;
        const float zd = __fdividef(zt - pzg[s], szg[s] + EPS);
        // l2w = log2(op * exp(-0.5 zd^2)) computed directly in log2 domain
        float l2w = fmaf(zd * zd, NHALF_LOG2E, __log2f(opg[s]));
        if (!(fabsf(zd) < Z_THRESHOLD)) l2w = -__int_as_float(0x7F800000);

        // Division-free row cull: top > CULL_LOG2
        //   <=>  (C(fy-px))^2 < (l2w - CULL_LOG2)(sx+EPS)^2
        const float t   = (fy - pxg[s]) * SCALE_C;
        const float sxe = sxg[s] + EPS;
        kp[s] = (t * t < (l2w - CULL_LOG2) * (sxe * sxe));  // -inf -> false

        // l2w <= 0 always (w < 1): for negative floats ascending raw bits ==
        // descending value, so ascending uint64 == descending eff_w with
        // ascending original idx on ties (stable argsort).
        kk[s] = ((unsigned long long)__float_as_uint(l2w) << 32)
              | (unsigned int)g;
    }

    // ---- warp-count compaction of survivor keys ----
    const unsigned int m0 = __ballot_sync(0xFFFFFFFFu, kp[0]);
    const unsigned int m1 = __ballot_sync(0xFFFFFFFFu, kp[1]);
    if (lane == 0) warpCnt[wid] = __popc(m0) + __popc(m1);
    __syncthreads();

    int base = 0, Mc = 0;
    #pragma unroll
    for (int ww = 0; ww < NWARP; ++ww) {
        const int c = warpCnt[ww];
        Mc += c;
        if (ww < wid) base += c;
    }
    const unsigned int ltmask = (1u << lane) - 1u;
    if (kp[0]) sk[base + __popc(m0 & ltmask)] = kk[0];
    if (kp[1]) sk[base + __popc(m0) + __popc(m1 & ltmask)] = kk[1];
    __syncthreads();

    // ---- rank sort over the Mc survivors; heavy math here only ----
    for (int i = tid; i < Mc; i += TPB) {
        const unsigned long long mykey = sk[i];
        int rank = 0;
        for (int j = 0; j < Mc; ++j) {
            rank += (sk[j] < mykey);   // broadcast LDS, unique keys
        }
        const int g = (int)(mykey & 0xFFFFFFFFull);
        const float l2w = __uint_as_float((unsigned int)(mykey >> 32));
        const float px = positions[g * 3 + 0];       // cache-hot reload
        const float py = positions[g * 3 + 1];
        const float sx = scales[g * 3 + 0];
        const float sy = scales[g * 3 + 1];
        const float isx = __fdividef(SCALE_C, sx + EPS);
        const float isy = __fdividef(SCALE_C, sy + EPS);
        const float dxp = (fy - px) * isx;
        const float top = fmaf(dxp, -dxp, l2w);      // log2w - dx'^2
        csp[rank] = make_float4(isy, -py * isy, top, intensity[g]);
    }
    __syncthreads();

    // ---- render: one pixel per thread ----
    const float fx = (float)tid;          // column (positions[:,1])

    float T = 1.0f;
    float A = 0.0f;

    #pragma unroll 4
    for (int j = 0; j < Mc; ++j) {
        const float4 P = csp[j];

        float dy  = fmaf(fx, P.x, P.y);        // (fx - py) * isy'
        float arg = fmaf(dy, -dy, P.z);        // top - dy'^2

        float ga;                              // == gauss * eff_w
        asm("ex2.approx.ftz.f32 %0, %1;" : "=f"(ga) : "f"(arg));

        float a  = fminf(ga, 0.99f);
        float ta = T * a;
        A = fmaf(ta, P.w, A);
        T -= ta;
    }

    out[blockIdx.x * W + tid] = A;
}

extern "C" void kernel_launch(void* const* d_in, const int* in_sizes, int n_in,
                              void* d_out, int out_size)
{
    const float* positions = (const float*)d_in[0];
    const float* scales    = (const float*)d_in[1];
    const float* opacity   = (const float*)d_in[2];
    const float* intensity = (const float*)d_in[3];
    const float* z_target  = (const float*)d_in[4];
    float* out = (float*)d_out;

    fused_kernel<<<GRID, TPB>>>(positions, scales, opacity, intensity,
                                z_target, out);
}